// round 6
// baseline (speedup 1.0000x reference)
#include <cuda_runtime.h>
#include <cstdint>
#include <cstddef>

#define NN    10000
#define KNBR  16
#define LDGG  10016
#define NBLD  1792
#define EE    (NN*KNBR)

typedef unsigned long long u64;

// NB column blocks (256 each): 0:Qa 1:Qb(+bq) 2:Ka 3:Kb(+bk) 4:P(+b1) 5:R 6:S(+b2)
static __device__ float  g_G[(size_t)NN * LDGG];     // Gram scratch
static __device__ float  g_NB[(size_t)NN * NBLD];    // node features
static __device__ float2 g_x2[(size_t)NN * 256];     // x pre-split {hi,lo}
static __device__ float2 g_WT2[(size_t)NBLD * 256];  // Wcat^T pre-split [n][k]
static __device__ float  g_bias[NBLD];
static __device__ float  g_n2[NN];
static __device__ int    g_nbr[EE];
static __device__ float  g_U[(size_t)EE * 256];      // relu(P_i+R_j) @ W2

// ---------------------------------------------------------------------------
// tf32 helpers (arch-agnostic PTX)
// ---------------------------------------------------------------------------
__device__ __forceinline__ uint32_t f2tf(float v) {
    uint32_t u; asm("cvt.rna.tf32.f32 %0, %1;" : "=r"(u) : "f"(v)); return u;
}
__device__ __forceinline__ float2 split_tf(float v) {
    uint32_t hi = f2tf(v);
    uint32_t lo = f2tf(v - __uint_as_float(hi));
    return make_float2(__uint_as_float(hi), __uint_as_float(lo));
}
__device__ __forceinline__ void mma8(float c[4], const uint32_t a[4], uint32_t b0, uint32_t b1) {
    asm volatile(
        "mma.sync.aligned.m16n8k8.row.col.f32.tf32.tf32.f32 "
        "{%0,%1,%2,%3}, {%4,%5,%6,%7}, {%8,%9}, {%0,%1,%2,%3};"
        : "+f"(c[0]), "+f"(c[1]), "+f"(c[2]), "+f"(c[3])
        : "r"(a[0]), "r"(a[1]), "r"(a[2]), "r"(a[3]), "r"(b0), "r"(b1));
}

// K=32 chunk, 3-pass tf32, tiles pre-split as float2{hi,lo}.
// As[k][m], Bs[k][n], padded to 132. Warp tile 64x32 at (wm*64, wn*32).
__device__ __forceinline__ void mma_chunk2(const float2 (*As)[132], const float2 (*Bs)[132],
                                           int wm, int wn, int lane, float c[4][4][4]) {
    int r  = lane >> 2;
    int cl = lane & 3;
    #pragma unroll
    for (int kc = 0; kc < 32; kc += 8) {
        uint32_t bh[4][2], bl[4][2];
        #pragma unroll
        for (int nf = 0; nf < 4; nf++) {
            int cb = wn * 32 + nf * 8;
            float2 g0 = Bs[kc + cl][cb + r];
            float2 g1 = Bs[kc + cl + 4][cb + r];
            bh[nf][0] = __float_as_uint(g0.x); bl[nf][0] = __float_as_uint(g0.y);
            bh[nf][1] = __float_as_uint(g1.x); bl[nf][1] = __float_as_uint(g1.y);
        }
        #pragma unroll
        for (int mf = 0; mf < 4; mf++) {
            int rb = wm * 64 + mf * 16;
            float2 f0 = As[kc + cl][rb + r];
            float2 f1 = As[kc + cl][rb + r + 8];
            float2 f2 = As[kc + cl + 4][rb + r];
            float2 f3 = As[kc + cl + 4][rb + r + 8];
            uint32_t ah[4] = {__float_as_uint(f0.x), __float_as_uint(f1.x),
                              __float_as_uint(f2.x), __float_as_uint(f3.x)};
            uint32_t al[4] = {__float_as_uint(f0.y), __float_as_uint(f1.y),
                              __float_as_uint(f2.y), __float_as_uint(f3.y)};
            #pragma unroll
            for (int nf = 0; nf < 4; nf++) {
                mma8(c[mf][nf], ah, bh[nf][0], bh[nf][1]);   // hi*hi
                mma8(c[mf][nf], al, bh[nf][0], bh[nf][1]);   // lo*hi
                mma8(c[mf][nf], ah, bl[nf][0], bl[nf][1]);   // hi*lo
            }
        }
    }
}

// ---------------------------------------------------------------------------
// Prep kernels
// ---------------------------------------------------------------------------
__global__ void split_x_kernel(const float* __restrict__ x) {
    int idx = blockIdx.x * 256 + threadIdx.x;
    g_x2[idx] = split_tf(x[idx]);
}

__global__ void build_wT_kernel(const float* __restrict__ Wq,
                                const float* __restrict__ Wk,
                                const float* __restrict__ W1,
                                const float* __restrict__ W2) {
    int idx = blockIdx.x * 256 + threadIdx.x;   // over NBLD*256
    int n = idx >> 8;     // output channel
    int k = idx & 255;    // input channel
    int b = n >> 8, c = n & 255;
    float v;
    switch (b) {
        case 0: v = Wq[(size_t)k * 256 + c];         break;
        case 1: v = Wq[(size_t)(k + 256) * 256 + c]; break;
        case 2: v = Wk[(size_t)k * 256 + c];         break;
        case 3: v = Wk[(size_t)(k + 256) * 256 + c]; break;
        case 4: v = W1[(size_t)k * 256 + c];         break;
        case 5: v = W1[(size_t)(k + 256) * 256 + c]; break;
        default: v = W2[(size_t)k * 256 + c];        break;
    }
    g_WT2[(size_t)n * 256 + k] = split_tf(v);
}

__global__ void build_bias_kernel(const float* __restrict__ bq,
                                  const float* __restrict__ bk,
                                  const float* __restrict__ b1,
                                  const float* __restrict__ b2) {
    int n = blockIdx.x * 256 + threadIdx.x;
    int b = n >> 8, c = n & 255;
    float v = 0.f;
    if (b == 1) v = bq[c];
    else if (b == 3) v = bk[c];
    else if (b == 4) v = b1[c];
    else if (b == 6) v = b2[c];
    g_bias[n] = v;
}

__global__ void norms_kernel(const float* __restrict__ x) {
    int row  = blockIdx.x * 8 + (threadIdx.x >> 5);
    int lane = threadIdx.x & 31;
    const float4* xr = (const float4*)(x + (size_t)row * 256);
    float s = 0.f;
    #pragma unroll
    for (int r = 0; r < 2; r++) {
        float4 v = xr[lane + 32 * r];
        s += v.x * v.x + v.y * v.y + v.z * v.z + v.w * v.w;
    }
    #pragma unroll
    for (int o = 16; o; o >>= 1) s += __shfl_xor_sync(0xffffffffu, s, o);
    if (lane == 0) g_n2[row] = s;
}

// ---------------------------------------------------------------------------
// Node GEMM: g_NB[m][n] = x[m].WT[n] + bias[n].  grid (14, 79), 256 thr.
// dyn smem: As2[32][132] + Bs2[32][132] float2 = 67584 B
// ---------------------------------------------------------------------------
__global__ void __launch_bounds__(256, 2) node_mma_kernel() {
    extern __shared__ __align__(16) char smem_raw[];
    float2 (*As2)[132] = (float2(*)[132])smem_raw;
    float2 (*Bs2)[132] = (float2(*)[132])(smem_raw + 32 * 132 * sizeof(float2));

    int t = threadIdx.x, lane = t & 31, wid = t >> 5;
    int wm = wid >> 2, wn = wid & 3;
    int m0 = blockIdx.y * 128, n0 = blockIdx.x * 128;

    float c[4][4][4];
    #pragma unroll
    for (int a = 0; a < 4; a++)
        #pragma unroll
        for (int b = 0; b < 4; b++)
            #pragma unroll
            for (int d = 0; d < 4; d++) c[a][b][d] = 0.f;

    int lr = t >> 1, lk = (t & 1) * 16;
    int arow = (m0 + lr < NN) ? (m0 + lr) : (NN - 1);
    const float2* ap = g_x2 + (size_t)arow * 256 + lk;
    const float2* bp = g_WT2 + (size_t)(n0 + lr) * 256 + lk;

    for (int k0 = 0; k0 < 256; k0 += 32) {
        const float4* a4 = (const float4*)(ap + k0);
        const float4* b4 = (const float4*)(bp + k0);
        #pragma unroll
        for (int q = 0; q < 8; q++) {
            float4 v = a4[q];
            As2[lk + 2 * q + 0][lr] = make_float2(v.x, v.y);
            As2[lk + 2 * q + 1][lr] = make_float2(v.z, v.w);
            float4 w = b4[q];
            Bs2[lk + 2 * q + 0][lr] = make_float2(w.x, w.y);
            Bs2[lk + 2 * q + 1][lr] = make_float2(w.z, w.w);
        }
        __syncthreads();
        mma_chunk2(As2, Bs2, wm, wn, lane, c);
        __syncthreads();
    }

    int r = lane >> 2, q = lane & 3;
    #pragma unroll
    for (int mf = 0; mf < 4; mf++) {
        #pragma unroll
        for (int nf = 0; nf < 4; nf++) {
            int row = m0 + wm * 64 + mf * 16 + r;
            int col = n0 + wn * 32 + nf * 8 + 2 * q;
            float b0 = g_bias[col], b1 = g_bias[col + 1];
            if (row < NN)
                *(float2*)(g_NB + (size_t)row * NBLD + col) =
                    make_float2(c[mf][nf][0] + b0, c[mf][nf][1] + b1);
            if (row + 8 < NN)
                *(float2*)(g_NB + (size_t)(row + 8) * NBLD + col) =
                    make_float2(c[mf][nf][2] + b0, c[mf][nf][3] + b1);
        }
    }
}

// ---------------------------------------------------------------------------
// Gram: G = x @ x^T, upper tiles + mirror.  grid (79, 79), 256 thr.
// ---------------------------------------------------------------------------
__global__ void __launch_bounds__(256, 2) gram_mma_kernel() {
    if (blockIdx.x < blockIdx.y) return;
    extern __shared__ __align__(16) char smem_raw[];
    float2 (*As2)[132] = (float2(*)[132])smem_raw;
    float2 (*Bs2)[132] = (float2(*)[132])(smem_raw + 32 * 132 * sizeof(float2));

    int t = threadIdx.x, lane = t & 31, wid = t >> 5;
    int wm = wid >> 2, wn = wid & 3;
    int m0 = blockIdx.y * 128, n0 = blockIdx.x * 128;
    bool diag = (blockIdx.x == blockIdx.y);

    float c[4][4][4];
    #pragma unroll
    for (int a = 0; a < 4; a++)
        #pragma unroll
        for (int b = 0; b < 4; b++)
            #pragma unroll
            for (int d = 0; d < 4; d++) c[a][b][d] = 0.f;

    int lr = t >> 1, lk = (t & 1) * 16;
    int arow = (m0 + lr < NN) ? (m0 + lr) : (NN - 1);
    int brow = (n0 + lr < NN) ? (n0 + lr) : (NN - 1);
    const float2* ap = g_x2 + (size_t)arow * 256 + lk;
    const float2* bp = g_x2 + (size_t)brow * 256 + lk;

    for (int k0 = 0; k0 < 256; k0 += 32) {
        const float4* a4 = (const float4*)(ap + k0);
        const float4* b4 = (const float4*)(bp + k0);
        #pragma unroll
        for (int q = 0; q < 8; q++) {
            float4 v = a4[q];
            As2[lk + 2 * q + 0][lr] = make_float2(v.x, v.y);
            As2[lk + 2 * q + 1][lr] = make_float2(v.z, v.w);
            float4 w = b4[q];
            Bs2[lk + 2 * q + 0][lr] = make_float2(w.x, w.y);
            Bs2[lk + 2 * q + 1][lr] = make_float2(w.z, w.w);
        }
        __syncthreads();
        mma_chunk2(As2, Bs2, wm, wn, lane, c);
        __syncthreads();
    }

    int r = lane >> 2, q = lane & 3;
    // direct store (upper tile)
    #pragma unroll
    for (int mf = 0; mf < 4; mf++) {
        #pragma unroll
        for (int nf = 0; nf < 4; nf++) {
            int row = m0 + wm * 64 + mf * 16 + r;
            int col = n0 + wn * 32 + nf * 8 + 2 * q;
            if (col + 1 < NN) {
                if (row < NN)
                    *(float2*)(g_G + (size_t)row * LDGG + col) =
                        make_float2(c[mf][nf][0], c[mf][nf][1]);
                if (row + 8 < NN)
                    *(float2*)(g_G + (size_t)(row + 8) * LDGG + col) =
                        make_float2(c[mf][nf][2], c[mf][nf][3]);
            } else if (col < NN) {
                if (row < NN)     g_G[(size_t)row * LDGG + col]       = c[mf][nf][0];
                if (row + 8 < NN) g_G[(size_t)(row + 8) * LDGG + col] = c[mf][nf][2];
            }
        }
    }

    // mirror store (off-diag); m rows always < NN (m0 <= 9856)
    if (!diag) {
        float* sT = (float*)smem_raw;             // [64][132] staging, reused
        for (int h = 0; h < 2; h++) {
            __syncthreads();
            if ((wn >> 1) == h) {
                #pragma unroll
                for (int mf = 0; mf < 4; mf++) {
                    #pragma unroll
                    for (int nf = 0; nf < 4; nf++) {
                        int rowl = wm * 64 + mf * 16 + r;
                        int cn   = (wn & 1) * 32 + nf * 8 + 2 * q;   // 0..63
                        sT[cn * 132 + rowl]           = c[mf][nf][0];
                        sT[(cn + 1) * 132 + rowl]     = c[mf][nf][1];
                        sT[cn * 132 + rowl + 8]       = c[mf][nf][2];
                        sT[(cn + 1) * 132 + rowl + 8] = c[mf][nf][3];
                    }
                }
            }
            __syncthreads();
            int n    = t >> 2;         // 0..63
            int part = t & 3;          // 32 floats each
            int gn = n0 + h * 64 + n;
            if (gn < NN) {
                const float* src = sT + n * 132 + part * 32;
                float* dst = g_G + (size_t)gn * LDGG + m0 + part * 32;
                #pragma unroll
                for (int j = 0; j < 8; j++)
                    *(float4*)(dst + 4 * j) = *(const float4*)(src + 4 * j);
            }
        }
    }
}

// ---------------------------------------------------------------------------
// Edge GEMM (fused relu(P_i+R_j), split at smem store): g_U = A @ W2
// grid (2, 1250), 256 thr.
// ---------------------------------------------------------------------------
__global__ void __launch_bounds__(256, 2) edge_mma_kernel() {
    extern __shared__ __align__(16) char smem_raw[];
    float2 (*As2)[132] = (float2(*)[132])smem_raw;
    float2 (*Bs2)[132] = (float2(*)[132])(smem_raw + 32 * 132 * sizeof(float2));

    int t = threadIdx.x, lane = t & 31, wid = t >> 5;
    int wm = wid >> 2, wn = wid & 3;
    int m0 = blockIdx.y * 128, n0 = blockIdx.x * 128;

    float c[4][4][4];
    #pragma unroll
    for (int a = 0; a < 4; a++)
        #pragma unroll
        for (int b = 0; b < 4; b++)
            #pragma unroll
            for (int d = 0; d < 4; d++) c[a][b][d] = 0.f;

    int lr = t >> 1, lk = (t & 1) * 16;
    int e = m0 + lr;                 // EE divisible by 128
    int inode = e >> 4;
    int jnode = g_nbr[e];
    const float* pp = g_NB + (size_t)inode * NBLD + 1024 + lk;    // P (+b1)
    const float* rp = g_NB + (size_t)jnode * NBLD + 1280 + lk;    // R
    const float2* bp = g_WT2 + (size_t)(1536 + n0 + lr) * 256 + lk;

    for (int k0 = 0; k0 < 256; k0 += 32) {
        #pragma unroll
        for (int jj = 0; jj < 4; jj++) {
            float4 pv = *(const float4*)(pp + k0 + 4 * jj);
            float4 rv = *(const float4*)(rp + k0 + 4 * jj);
            As2[lk + 4 * jj + 0][lr] = split_tf(fmaxf(pv.x + rv.x, 0.f));
            As2[lk + 4 * jj + 1][lr] = split_tf(fmaxf(pv.y + rv.y, 0.f));
            As2[lk + 4 * jj + 2][lr] = split_tf(fmaxf(pv.z + rv.z, 0.f));
            As2[lk + 4 * jj + 3][lr] = split_tf(fmaxf(pv.w + rv.w, 0.f));
        }
        const float4* b4 = (const float4*)(bp + k0);
        #pragma unroll
        for (int q = 0; q < 8; q++) {
            float4 w = b4[q];
            Bs2[lk + 2 * q + 0][lr] = make_float2(w.x, w.y);
            Bs2[lk + 2 * q + 1][lr] = make_float2(w.z, w.w);
        }
        __syncthreads();
        mma_chunk2(As2, Bs2, wm, wn, lane, c);
        __syncthreads();
    }

    int r = lane >> 2, q = lane & 3;
    #pragma unroll
    for (int mf = 0; mf < 4; mf++) {
        #pragma unroll
        for (int nf = 0; nf < 4; nf++) {
            int row = m0 + wm * 64 + mf * 16 + r;
            int col = n0 + wn * 32 + nf * 8 + 2 * q;
            *(float2*)(g_U + (size_t)row * 256 + col) =
                make_float2(c[mf][nf][0], c[mf][nf][1]);
            *(float2*)(g_U + (size_t)(row + 8) * 256 + col) =
                make_float2(c[mf][nf][2], c[mf][nf][3]);
        }
    }
}

// ---------------------------------------------------------------------------
// Exact top-16 per row via radix select (block per row, 256 threads)
// ---------------------------------------------------------------------------
__device__ __forceinline__ uint32_t fkey(float d) {
    uint32_t u = __float_as_uint(d);
    return u ^ ((u & 0x80000000u) ? 0xFFFFFFFFu : 0x80000000u);
}

__device__ __forceinline__ void hist_add(uint32_t* hist, uint32_t bin, bool act) {
    unsigned m = __ballot_sync(0xffffffffu, act);
    if (act) {
        unsigned same = __match_any_sync(m, bin);
        int leader = __ffs(same) - 1;
        if ((int)(threadIdx.x & 31) == leader) atomicAdd(&hist[bin], __popc(same));
    }
}

__global__ void __launch_bounds__(256) topk_kernel() {
    extern __shared__ float sd[];                 // NN floats (40000 B)
    __shared__ uint32_t s_hist[256];
    __shared__ uint32_t s_pref;
    __shared__ int s_kth, s_bincnt, s_shift, s_nout, s_ccnt;
    __shared__ u64 s_cand[256];

    int row = blockIdx.x, t = threadIdx.x, lane = t & 31;
    const float FINF = __int_as_float(0x7f800000);

    if (t < 256) s_hist[t] = 0;
    if (t == 0) { s_pref = 0; s_kth = 16; s_shift = 24; s_bincnt = 0; s_nout = 0; s_ccnt = 0; }
    __syncthreads();

    float n2i = g_n2[row];
    const float* Gr = g_G + (size_t)row * LDGG;

    // pass 1: distances + store + level-0 histogram
    for (int it = 0; it < 10; it++) {
        int j0 = t * 4 + it * 1024;
        bool act = j0 < NN;
        float d[4];
        if (act) {
            float4 g  = *(const float4*)(Gr + j0);
            float4 nn = *(const float4*)(g_n2 + j0);
            d[0] = n2i + nn.x - 2.f * g.x;
            d[1] = n2i + nn.y - 2.f * g.y;
            d[2] = n2i + nn.z - 2.f * g.z;
            d[3] = n2i + nn.w - 2.f * g.w;
            #pragma unroll
            for (int e2 = 0; e2 < 4; e2++) {
                if (j0 + e2 == row) d[e2] = FINF;
                sd[j0 + e2] = d[e2];
            }
        }
        #pragma unroll
        for (int e2 = 0; e2 < 4; e2++)
            hist_add(s_hist, act ? (fkey(d[e2]) >> 24) : 0u, act);
    }
    __syncthreads();

    // radix descent
    for (int lvl = 0; lvl < 4; lvl++) {
        if (t < 32) {
            int kth = s_kth;
            int base = lane * 8, s = 0;
            int h[8];
            #pragma unroll
            for (int q = 0; q < 8; q++) { h[q] = s_hist[base + q]; s += h[q]; }
            int scan = s;
            #pragma unroll
            for (int o = 1; o < 32; o <<= 1) {
                int v = __shfl_up_sync(0xffffffffu, scan, o);
                if (lane >= o) scan += v;
            }
            int excl = scan - s;
            if (kth > excl && kth <= excl + s) {
                int cacc = excl;
                #pragma unroll
                for (int q = 0; q < 8; q++) {
                    if (kth <= cacc + h[q]) {
                        s_pref |= (uint32_t)(base + q) << s_shift;
                        s_kth = kth - cacc;
                        s_bincnt = h[q];
                        break;
                    }
                    cacc += h[q];
                }
            }
        }
        __syncthreads();
        if (s_bincnt <= 64 || s_shift == 0) break;
        uint32_t pref = s_pref;
        int sh = s_shift;
        __syncthreads();
        if (t < 256) s_hist[t] = 0;
        if (t == 0) s_shift = sh - 8;
        __syncthreads();
        for (int it = 0; it < 10; it++) {
            int j0 = t * 4 + it * 1024;
            #pragma unroll
            for (int e2 = 0; e2 < 4; e2++) {
                int j = j0 + e2;
                bool act = j < NN;
                uint32_t key = act ? fkey(sd[j]) : 0u;
                act = act && ((key >> sh) == (pref >> sh));
                hist_add(s_hist, (key >> (sh - 8)) & 255u, act);
            }
        }
        __syncthreads();
    }

    // emit
    uint32_t pref = s_pref;
    int sh = s_shift;
    int kth = s_kth;
    uint32_t bkt = pref >> sh;
    for (int it = 0; it < 10; it++) {
        int j0 = t * 4 + it * 1024;
        #pragma unroll
        for (int e2 = 0; e2 < 4; e2++) {
            int j = j0 + e2;
            if (j < NN) {
                uint32_t key = fkey(sd[j]);
                uint32_t kb = key >> sh;
                if (kb < bkt) {
                    int slot = atomicAdd(&s_nout, 1);
                    g_nbr[row * 16 + slot] = j;
                } else if (kb == bkt) {
                    int cc = atomicAdd(&s_ccnt, 1);
                    if (cc < 256) s_cand[cc] = ((u64)key << 32) | (uint32_t)j;
                }
            }
        }
    }
    __syncthreads();

    if (t < 32) {
        int cc = min(s_ccnt, 256);
        int base_out = s_nout;
        for (int sel = 0; sel < kth; sel++) {
            u64 mv = ~0ull; int mi = -1;
            for (int p = lane; p < cc; p += 32) {
                u64 v = s_cand[p];
                if (v < mv) { mv = v; mi = p; }
            }
            #pragma unroll
            for (int o = 16; o; o >>= 1) {
                u64 ov = __shfl_xor_sync(0xffffffffu, mv, o);
                int oi = __shfl_xor_sync(0xffffffffu, mi, o);
                if (ov < mv) { mv = ov; mi = oi; }
            }
            if (lane == 0) {
                g_nbr[row * 16 + base_out + sel] = (int)(mv & 0xffffffffu);
                s_cand[mi] = ~0ull;
            }
            __syncwarp();
        }
    }
}

// ---------------------------------------------------------------------------
// Combine: ew per edge + mixing + mean aggregation (biases already folded)
// ---------------------------------------------------------------------------
__global__ void combine_kernel(float* __restrict__ out) {
    int i = blockIdx.x;
    int t = threadIdx.x;         // 0..127
    __shared__ float qb[256], kb[256], sb[256], ewsh[4];

    const float* nbi = g_NB + (size_t)i * NBLD;
    for (int c = t; c < 256; c += 128) {
        qb[c] = nbi[256 + c];
        kb[c] = nbi[768 + c];
        sb[c] = nbi[1536 + c];
    }
    __syncthreads();

    int w    = t >> 5;
    int lane = t & 31;
    int h = w >> 1, g = w & 1;

    float a0 = 0.f, a1 = 0.f;

    for (int kk = 0; kk < 16; kk++) {
        int e = i * 16 + kk;
        int j = g_nbr[e];
        const float* qaj = g_NB + (size_t)j * NBLD;
        const float* kaj = qaj + 512;
        float s = 0.f;
        #pragma unroll
        for (int r = 0; r < 4; r++) {
            int d = lane + 32 * r;
            float qv = qaj[h * 128 + d] + qb[h * 128 + d];
            float kv = kaj[g * 128 + d] + kb[g * 128 + d];
            s = fmaf(qv, kv, s);
        }
        #pragma unroll
        for (int o = 16; o; o >>= 1) s += __shfl_xor_sync(0xffffffffu, s, o);
        if (lane == 0) ewsh[w] = s * 0.0625f;
        __syncthreads();
        float e00 = ewsh[0], e01 = ewsh[1], e10 = ewsh[2], e11 = ewsh[3];
        float2 u2 = *(const float2*)&g_U[(size_t)e * 256 + 2 * t];
        float u0 = u2.x + sb[2 * t];
        float u1 = u2.y + sb[2 * t + 1];
        a0 += u0 * e00 + u1 * e10;
        a1 += u0 * e01 + u1 * e11;
        __syncthreads();
    }

    out[(size_t)i * 256 + 2 * t]     = a0 * 0.0625f;
    out[(size_t)i * 256 + 2 * t + 1] = a1 * 0.0625f;
}

// ---------------------------------------------------------------------------
// Launch
// ---------------------------------------------------------------------------
extern "C" void kernel_launch(void* const* d_in, const int* in_sizes, int n_in,
                              void* d_out, int out_size) {
    const float* x  = (const float*)d_in[0];
    const float* W1 = (const float*)d_in[1];
    const float* b1 = (const float*)d_in[2];
    const float* W2 = (const float*)d_in[3];
    const float* b2 = (const float*)d_in[4];
    const float* Wq = (const float*)d_in[5];
    const float* bq = (const float*)d_in[6];
    const float* Wk = (const float*)d_in[7];
    const float* bk = (const float*)d_in[8];
    float* out = (float*)d_out;

    const int GEMM_SMEM = 2 * 32 * 132 * (int)sizeof(float2);   // 67584
    const int TOPK_SMEM = NN * (int)sizeof(float);              // 40000
    cudaFuncSetAttribute(node_mma_kernel, cudaFuncAttributeMaxDynamicSharedMemorySize, GEMM_SMEM);
    cudaFuncSetAttribute(gram_mma_kernel, cudaFuncAttributeMaxDynamicSharedMemorySize, GEMM_SMEM);
    cudaFuncSetAttribute(edge_mma_kernel, cudaFuncAttributeMaxDynamicSharedMemorySize, GEMM_SMEM);
    cudaFuncSetAttribute(topk_kernel,     cudaFuncAttributeMaxDynamicSharedMemorySize, TOPK_SMEM);

    split_x_kernel<<<NN, 256>>>(x);
    build_wT_kernel<<<NBLD, 256>>>(Wq, Wk, W1, W2);
    build_bias_kernel<<<7, 256>>>(bq, bk, b1, b2);
    norms_kernel<<<1250, 256>>>(x);

    node_mma_kernel<<<dim3(14, 79), 256, GEMM_SMEM>>>();
    gram_mma_kernel<<<dim3(79, 79), 256, GEMM_SMEM>>>();
    topk_kernel<<<NN, 256, TOPK_SMEM>>>();
    edge_mma_kernel<<<dim3(2, 1250), 256, GEMM_SMEM>>>();
    combine_kernel<<<NN, 128>>>(out);
}